// round 4
// baseline (speedup 1.0000x reference)
#include <cuda_runtime.h>
#include <cstdint>

#define B_TOT 192
#define SEQ   256
#define CH    256
#define NH    8
#define HD    32
#define NW    64

// ---------------- scratch (device globals: allocation-free) ----------------
__device__ float g_qkv[(size_t)B_TOT * SEQ * 3 * CH];   // 37.7M floats (151 MB)
__device__ float g_attnout[(size_t)B_TOT * SEQ * CH];   // 12.6M floats (50 MB)
__device__ float g_bias[NH * SEQ * SEQ];                // 2 MB

// ---------------- helpers ----------------
__device__ __forceinline__ float tf32r(float f) {
    uint32_t u;
    asm("cvt.rna.tf32.f32 %0, %1;" : "=r"(u) : "f"(f));
    return __uint_as_float(u);
}

__device__ __forceinline__ void mma8(float* d, const uint32_t* a, const uint32_t* b) {
    asm volatile(
        "mma.sync.aligned.m16n8k8.row.col.f32.tf32.tf32.f32 "
        "{%0,%1,%2,%3},{%4,%5,%6,%7},{%8,%9},{%0,%1,%2,%3};\n"
        : "+f"(d[0]), "+f"(d[1]), "+f"(d[2]), "+f"(d[3])
        : "r"(a[0]), "r"(a[1]), "r"(a[2]), "r"(a[3]), "r"(b[0]), "r"(b[1]));
}

// ---------------- bias gather: g_bias[h][i][j] = table[idx[i,j]*8 + h] ------
__global__ void bias_kernel(const float* __restrict__ table, const int* __restrict__ idx) {
    int e = blockIdx.x * 256 + threadIdx.x;      // 8*65536 = 524288 total
    int h  = e >> 16;
    int ij = e & 65535;
    g_bias[e] = table[idx[ij] * NH + h];
}

// ---------------- TF32 GEMM: C[M,N] = A[M,K] * W[N,K]^T + bias[N] ----------
// block tile 128x64, K-step 32, 256 threads (8 warps, 4m x 2n, warp tile 32x32)
__global__ __launch_bounds__(256, 2) void gemm_tf32(
    const float* __restrict__ A, int lda,
    const float* __restrict__ W,
    const float* __restrict__ bias,
    float* __restrict__ C, int ldc, int K)
{
    __shared__ float As[128 * 36];
    __shared__ float Bs[64 * 36];

    const int tid  = threadIdx.x;
    const int wid  = tid >> 5;
    const int lane = tid & 31;
    const int g    = lane >> 2;
    const int t    = lane & 3;
    const int wm   = (wid >> 1) * 32;
    const int wn   = (wid & 1) * 32;
    const int bm   = blockIdx.x * 128;
    const int bn   = blockIdx.y * 64;

    const int r8 = tid >> 3;
    const int c4 = (tid & 7) * 4;

    float acc[2][4][4];
    #pragma unroll
    for (int mi = 0; mi < 2; mi++)
        #pragma unroll
        for (int ni = 0; ni < 4; ni++)
            #pragma unroll
            for (int e = 0; e < 4; e++) acc[mi][ni][e] = 0.f;

    float4 ra[4], rb[2];

    auto loadA = [&](int k0) {
        #pragma unroll
        for (int i = 0; i < 4; i++)
            ra[i] = *(const float4*)(A + (size_t)(bm + r8 + i * 32) * lda + k0 + c4);
    };
    auto loadB = [&](int k0) {
        #pragma unroll
        for (int i = 0; i < 2; i++)
            rb[i] = *(const float4*)(W + (size_t)(bn + r8 + i * 32) * K + k0 + c4);
    };

    loadA(0);
    loadB(0);

    for (int k0 = 0; k0 < K; k0 += 32) {
        #pragma unroll
        for (int i = 0; i < 4; i++) {
            float4 v = ra[i];
            v.x = tf32r(v.x); v.y = tf32r(v.y); v.z = tf32r(v.z); v.w = tf32r(v.w);
            *(float4*)(As + (r8 + i * 32) * 36 + c4) = v;
        }
        #pragma unroll
        for (int i = 0; i < 2; i++) {
            float4 v = rb[i];
            v.x = tf32r(v.x); v.y = tf32r(v.y); v.z = tf32r(v.z); v.w = tf32r(v.w);
            *(float4*)(Bs + (r8 + i * 32) * 36 + c4) = v;
        }
        __syncthreads();

        if (k0 + 32 < K) { loadA(k0 + 32); loadB(k0 + 32); }

        #pragma unroll
        for (int kk = 0; kk < 4; kk++) {
            uint32_t af[2][4];
            #pragma unroll
            for (int mi = 0; mi < 2; mi++) {
                int r0 = wm + mi * 16 + g;
                af[mi][0] = __float_as_uint(As[r0 * 36 + kk * 8 + t]);
                af[mi][1] = __float_as_uint(As[(r0 + 8) * 36 + kk * 8 + t]);
                af[mi][2] = __float_as_uint(As[r0 * 36 + kk * 8 + t + 4]);
                af[mi][3] = __float_as_uint(As[(r0 + 8) * 36 + kk * 8 + t + 4]);
            }
            #pragma unroll
            for (int ni = 0; ni < 4; ni++) {
                int n0 = wn + ni * 8 + g;
                uint32_t bf[2];
                bf[0] = __float_as_uint(Bs[n0 * 36 + kk * 8 + t]);
                bf[1] = __float_as_uint(Bs[n0 * 36 + kk * 8 + t + 4]);
                mma8(acc[0][ni], af[0], bf);
                mma8(acc[1][ni], af[1], bf);
            }
        }
        __syncthreads();
    }

    #pragma unroll
    for (int mi = 0; mi < 2; mi++)
        #pragma unroll
        for (int ni = 0; ni < 4; ni++) {
            int r = bm + wm + mi * 16 + g;
            int c = bn + wn + ni * 8 + 2 * t;
            float b0 = bias[c], b1 = bias[c + 1];
            float2 v0 = make_float2(acc[mi][ni][0] + b0, acc[mi][ni][1] + b1);
            float2 v1 = make_float2(acc[mi][ni][2] + b0, acc[mi][ni][3] + b1);
            *(float2*)(C + (size_t)r * ldc + c) = v0;
            *(float2*)(C + (size_t)(r + 8) * ldc + c) = v1;
        }
}

// ---------------- fused window attention ----------------
// grid (4 row-tiles, 8 heads, 192 windows), 256 threads.
// S = (Q*scale) K^T (+bias+mask) -> exact row softmax -> O = P V
#define ATT_SMEM ((64 * 36 + 256 * 36 + 256 * 40 + 64 * 260) * 4)

__global__ __launch_bounds__(256, 1) void attn_kernel(const float* __restrict__ mask) {
    extern __shared__ float sm[];
    float* Qs = sm;                       // 64  x 36
    float* Ks = Qs + 64 * 36;             // 256 x 36
    float* Vs = Ks + 256 * 36;            // 256 x 40
    float* Ps = Vs + 256 * 40;            // 64  x 260

    const int rt = blockIdx.x;
    const int h  = blockIdx.y;
    const int b  = blockIdx.z;
    const int w  = b & (NW - 1);

    const int tid  = threadIdx.x;
    const int wid  = tid >> 5;
    const int lane = tid & 31;
    const int g    = lane >> 2;
    const int t    = lane & 3;
    const float scale = 0.17677669529663687f;   // 32^-0.5

    const float* base = g_qkv + (size_t)b * SEQ * 768;
    const int r8 = tid >> 3;
    const int c4 = (tid & 7) * 4;

    // ---- stage Q (pre-scaled), K, V into smem as tf32-rounded fp32 ----
    #pragma unroll
    for (int i = 0; i < 2; i++) {
        int row = r8 + i * 32;
        float4 v = *(const float4*)(base + (size_t)(rt * 64 + row) * 768 + h * HD + c4);
        v.x = tf32r(v.x * scale); v.y = tf32r(v.y * scale);
        v.z = tf32r(v.z * scale); v.w = tf32r(v.w * scale);
        *(float4*)(Qs + row * 36 + c4) = v;
    }
    #pragma unroll
    for (int i = 0; i < 8; i++) {
        int row = r8 + i * 32;
        float4 v = *(const float4*)(base + (size_t)row * 768 + CH + h * HD + c4);
        v.x = tf32r(v.x); v.y = tf32r(v.y); v.z = tf32r(v.z); v.w = tf32r(v.w);
        *(float4*)(Ks + row * 36 + c4) = v;
    }
    #pragma unroll
    for (int i = 0; i < 8; i++) {
        int row = r8 + i * 32;
        float4 v = *(const float4*)(base + (size_t)row * 768 + 2 * CH + h * HD + c4);
        v.x = tf32r(v.x); v.y = tf32r(v.y); v.z = tf32r(v.z); v.w = tf32r(v.w);
        *(float4*)(Vs + row * 40 + c4) = v;
    }
    __syncthreads();

    // ---- S = Q K^T : warps 2(m) x 4(n), warp tile 32x64 ----
    {
        const int wm = (wid >> 2) * 32;
        const int wn = (wid & 3) * 64;
        float sacc[2][8][4];
        #pragma unroll
        for (int mi = 0; mi < 2; mi++)
            #pragma unroll
            for (int ni = 0; ni < 8; ni++)
                #pragma unroll
                for (int e = 0; e < 4; e++) sacc[mi][ni][e] = 0.f;

        #pragma unroll
        for (int kk = 0; kk < 4; kk++) {
            uint32_t af[2][4];
            #pragma unroll
            for (int mi = 0; mi < 2; mi++) {
                int r0 = wm + mi * 16 + g;
                af[mi][0] = __float_as_uint(Qs[r0 * 36 + kk * 8 + t]);
                af[mi][1] = __float_as_uint(Qs[(r0 + 8) * 36 + kk * 8 + t]);
                af[mi][2] = __float_as_uint(Qs[r0 * 36 + kk * 8 + t + 4]);
                af[mi][3] = __float_as_uint(Qs[(r0 + 8) * 36 + kk * 8 + t + 4]);
            }
            #pragma unroll
            for (int ni = 0; ni < 8; ni++) {
                int n0 = wn + ni * 8 + g;
                uint32_t bf[2];
                bf[0] = __float_as_uint(Ks[n0 * 36 + kk * 8 + t]);
                bf[1] = __float_as_uint(Ks[n0 * 36 + kk * 8 + t + 4]);
                mma8(sacc[0][ni], af[0], bf);
                mma8(sacc[1][ni], af[1], bf);
            }
        }

        #pragma unroll
        for (int mi = 0; mi < 2; mi++)
            #pragma unroll
            for (int ni = 0; ni < 8; ni++) {
                int i0 = wm + mi * 16 + g;
                int c  = wn + ni * 8 + 2 * t;
                *(float2*)(Ps + i0 * 260 + c)       = make_float2(sacc[mi][ni][0], sacc[mi][ni][1]);
                *(float2*)(Ps + (i0 + 8) * 260 + c) = make_float2(sacc[mi][ni][2], sacc[mi][ni][3]);
            }
    }
    __syncthreads();

    // ---- softmax over full rows (exact fp32), bias+mask added here ----
    {
        #pragma unroll 1
        for (int rr = 0; rr < 8; rr++) {
            int r  = wid * 8 + rr;
            int ig = rt * 64 + r;
            const float* brow = g_bias + ((size_t)h * SEQ + ig) * SEQ;
            const float* mrow = mask + ((size_t)w * SEQ + ig) * SEQ;
            float vals[8];
            float mx = -1e30f;
            #pragma unroll
            for (int u = 0; u < 8; u++) {
                int c = lane + u * 32;
                float x = Ps[r * 260 + c] + brow[c] + mrow[c];
                vals[u] = x;
                mx = fmaxf(mx, x);
            }
            #pragma unroll
            for (int off = 16; off > 0; off >>= 1)
                mx = fmaxf(mx, __shfl_xor_sync(0xffffffffu, mx, off));
            float s = 0.f;
            #pragma unroll
            for (int u = 0; u < 8; u++) {
                float e = __expf(vals[u] - mx);
                vals[u] = e;
                s += e;
            }
            #pragma unroll
            for (int off = 16; off > 0; off >>= 1)
                s += __shfl_xor_sync(0xffffffffu, s, off);
            float inv = 1.f / s;
            #pragma unroll
            for (int u = 0; u < 8; u++)
                Ps[r * 260 + lane + u * 32] = tf32r(vals[u] * inv);
        }
    }
    __syncthreads();

    // ---- O = P V : warps 4(m) x 2(n), warp tile 16x16 ----
    {
        const int wm2 = (wid >> 1) * 16;
        const int wn2 = (wid & 1) * 16;
        float oacc[2][4];
        #pragma unroll
        for (int ni = 0; ni < 2; ni++)
            #pragma unroll
            for (int e = 0; e < 4; e++) oacc[ni][e] = 0.f;

        #pragma unroll 8
        for (int kk = 0; kk < 32; kk++) {
            uint32_t af[4];
            int r0 = wm2 + g;
            af[0] = __float_as_uint(Ps[r0 * 260 + kk * 8 + t]);
            af[1] = __float_as_uint(Ps[(r0 + 8) * 260 + kk * 8 + t]);
            af[2] = __float_as_uint(Ps[r0 * 260 + kk * 8 + t + 4]);
            af[3] = __float_as_uint(Ps[(r0 + 8) * 260 + kk * 8 + t + 4]);
            #pragma unroll
            for (int ni = 0; ni < 2; ni++) {
                int n0 = wn2 + ni * 8 + g;
                uint32_t bf[2];
                bf[0] = __float_as_uint(Vs[(kk * 8 + t) * 40 + n0]);
                bf[1] = __float_as_uint(Vs[(kk * 8 + t + 4) * 40 + n0]);
                mma8(oacc[ni], af, bf);
            }
        }

        #pragma unroll
        for (int ni = 0; ni < 2; ni++) {
            int i = wm2 + g;
            int d = wn2 + ni * 8 + 2 * t;
            size_t o0 = (size_t)(b * SEQ + rt * 64 + i) * CH + h * HD + d;
            *(float2*)(g_attnout + o0)            = make_float2(oacc[ni][0], oacc[ni][1]);
            *(float2*)(g_attnout + o0 + 8 * CH)   = make_float2(oacc[ni][2], oacc[ni][3]);
        }
    }
}

// ---------------- launch ----------------
extern "C" void kernel_launch(void* const* d_in, const int* in_sizes, int n_in,
                              void* d_out, int out_size)
{
    const float* x      = (const float*)d_in[0];
    const float* mask   = (const float*)d_in[1];
    const float* qkv_w  = (const float*)d_in[2];
    const float* qkv_b  = (const float*)d_in[3];
    const float* proj_w = (const float*)d_in[4];
    const float* proj_b = (const float*)d_in[5];
    const float* table  = (const float*)d_in[6];
    const int*   rpi    = (const int*)d_in[7];
    float* out = (float*)d_out;
    (void)in_sizes; (void)n_in; (void)out_size;

    float *qkv_p, *ao_p;
    cudaGetSymbolAddress((void**)&qkv_p, g_qkv);
    cudaGetSymbolAddress((void**)&ao_p, g_attnout);

    cudaFuncSetAttribute(attn_kernel, cudaFuncAttributeMaxDynamicSharedMemorySize, ATT_SMEM);

    // 1) relative-position bias gather (H,N,N)
    bias_kernel<<<2048, 256>>>(table, rpi);

    // 2) QKV projection: (49152 x 256) x (768 x 256)^T + b  -> g_qkv
    gemm_tf32<<<dim3(384, 12), 256>>>(x, CH, qkv_w, qkv_b, qkv_p, 3 * CH, CH);

    // 3) fused window attention -> g_attnout (B, N, C layout)
    attn_kernel<<<dim3(4, NH, B_TOT), 256, ATT_SMEM>>>(mask);

    // 4) output projection: (49152 x 256) x (256 x 256)^T + b -> d_out
    gemm_tf32<<<dim3(384, 4), 256>>>(ao_p, CH, proj_w, proj_b, out, CH, CH);
}

// round 5
// speedup vs baseline: 1.6946x; 1.6946x over previous
#include <cuda_runtime.h>
#include <cuda_fp16.h>
#include <cstdint>

#define SCALE 0.17677669529663687f

// ---------------- scratch (device globals: allocation-free) ----------------
__device__ __half g_xh[(size_t)49152 * 256];       // x in half          (25 MB)
__device__ __half g_qkvwh[768 * 256];              // qkv_w half, q rows pre-scaled
__device__ __half g_projwh[256 * 256];             // proj_w half
__device__ float  g_qkvb[768];                     // qkv_b, q part pre-scaled
__device__ __half g_qkv[(size_t)49152 * 768];      // qkv output half    (75.5 MB)
__device__ __half g_attnout[(size_t)49152 * 256];  // attention out half (25 MB)
__device__ float  g_bias[8 * 256 * 256];           // rel-pos bias (H,N,N) fp32

// ---------------- helpers ----------------
__device__ __forceinline__ void mma16(float* d, const uint32_t* a, const uint32_t* b) {
    asm volatile(
        "mma.sync.aligned.m16n8k16.row.col.f32.f16.f16.f32 "
        "{%0,%1,%2,%3},{%4,%5,%6,%7},{%8,%9},{%0,%1,%2,%3};\n"
        : "+f"(d[0]), "+f"(d[1]), "+f"(d[2]), "+f"(d[3])
        : "r"(a[0]), "r"(a[1]), "r"(a[2]), "r"(a[3]), "r"(b[0]), "r"(b[1]));
}

__device__ __forceinline__ void cp16(uint32_t dst, const void* src) {
    asm volatile("cp.async.ca.shared.global [%0], [%1], 16;\n" :: "r"(dst), "l"(src));
}
__device__ __forceinline__ void cp_commit() { asm volatile("cp.async.commit_group;\n"); }
__device__ __forceinline__ void cp_wait0()  { asm volatile("cp.async.wait_group 0;\n"); }
__device__ __forceinline__ void cp_wait1()  { asm volatile("cp.async.wait_group 1;\n"); }

// ---------------- converts ----------------
__global__ void cvt_x(const float4* __restrict__ x) {
    int i = blockIdx.x * 256 + threadIdx.x;          // 3145728 float4s
    float4 v = x[i];
    __half2 a = __floats2half2_rn(v.x, v.y);
    __half2 c = __floats2half2_rn(v.z, v.w);
    uint2 u;
    u.x = *reinterpret_cast<uint32_t*>(&a);
    u.y = *reinterpret_cast<uint32_t*>(&c);
    ((uint2*)g_xh)[i] = u;
}

__global__ void cvt_qkvw(const float* __restrict__ w, const float* __restrict__ bvec) {
    int i = blockIdx.x * 256 + threadIdx.x;          // 196608
    float s = (i < 65536) ? SCALE : 1.0f;            // q rows get the scale folded in
    g_qkvwh[i] = __float2half(w[i] * s);
    if (i < 768) g_qkvb[i] = bvec[i] * ((i < 256) ? SCALE : 1.0f);
}

__global__ void cvt_projw(const float* __restrict__ w) {
    int i = blockIdx.x * 256 + threadIdx.x;          // 65536
    g_projwh[i] = __float2half(w[i]);
}

// ---------------- bias gather: g_bias[h][i][j] = table[idx[i,j]*8 + h] ------
__global__ void bias_kernel(const float* __restrict__ table, const int* __restrict__ idx) {
    int e = blockIdx.x * 256 + threadIdx.x;          // 524288
    int h  = e >> 16;
    int ij = e & 65535;
    g_bias[e] = table[idx[ij] * 8 + h];
}

// ---------------- FP16 GEMM: C[M,N] = A[M,256] * W[N,256]^T + bias[N] -------
// block 128x128, k-step 32, 256 threads, warps 2m x 4n (64x32), cp.async 2-buf
template <bool HOUT>
__global__ __launch_bounds__(256, 2) void gemm_h(
    const __half* __restrict__ A,
    const __half* __restrict__ W,
    const float* __restrict__ bias,
    void* __restrict__ Cv, int ldc)
{
    __shared__ __half Asm[2][128 * 40];
    __shared__ __half Bsm[2][128 * 40];

    const int tid  = threadIdx.x;
    const int wid  = tid >> 5;
    const int lane = tid & 31;
    const int g    = lane >> 2;
    const int t    = lane & 3;
    const int wm   = (wid >> 2) * 64;
    const int wn   = (wid & 3) * 32;
    const int bm   = blockIdx.x * 128;
    const int bn   = blockIdx.y * 128;

    const uint32_t abase = (uint32_t)__cvta_generic_to_shared(Asm);
    const uint32_t bbase = (uint32_t)__cvta_generic_to_shared(Bsm);

    auto stage = [&](int buf, int k0) {
        #pragma unroll
        for (int j = 0; j < 2; j++) {
            int id  = tid + j * 256;                 // 512 x 16B per tile
            int row = id >> 2, seg = id & 3;
            cp16(abase + buf * 10240 + row * 80 + seg * 16,
                 A + (size_t)(bm + row) * 256 + k0 + seg * 8);
            cp16(bbase + buf * 10240 + row * 80 + seg * 16,
                 W + (size_t)(bn + row) * 256 + k0 + seg * 8);
        }
        cp_commit();
    };

    float acc[4][4][4];
    #pragma unroll
    for (int mi = 0; mi < 4; mi++)
        #pragma unroll
        for (int ni = 0; ni < 4; ni++)
            #pragma unroll
            for (int e = 0; e < 4; e++) acc[mi][ni][e] = 0.f;

    stage(0, 0);
    stage(1, 32);

    #pragma unroll 1
    for (int i = 0; i < 8; i++) {
        if (i < 7) cp_wait1(); else cp_wait0();
        __syncthreads();
        const __half* As = Asm[i & 1];
        const __half* Bs = Bsm[i & 1];

        #pragma unroll
        for (int kc = 0; kc < 2; kc++) {
            uint32_t af[4][4];
            #pragma unroll
            for (int mi = 0; mi < 4; mi++) {
                const __half* p = As + (wm + mi * 16 + g) * 40 + kc * 16 + 2 * t;
                af[mi][0] = *(const uint32_t*)p;
                af[mi][1] = *(const uint32_t*)(p + 8 * 40);
                af[mi][2] = *(const uint32_t*)(p + 8);
                af[mi][3] = *(const uint32_t*)(p + 8 * 40 + 8);
            }
            #pragma unroll
            for (int ni = 0; ni < 4; ni++) {
                const __half* p = Bs + (wn + ni * 8 + g) * 40 + kc * 16 + 2 * t;
                uint32_t bf[2];
                bf[0] = *(const uint32_t*)p;
                bf[1] = *(const uint32_t*)(p + 8);
                #pragma unroll
                for (int mi = 0; mi < 4; mi++) mma16(acc[mi][ni], af[mi], bf);
            }
        }
        __syncthreads();
        if (i + 2 < 8) stage(i & 1, (i + 2) * 32);
    }

    #pragma unroll
    for (int mi = 0; mi < 4; mi++)
        #pragma unroll
        for (int ni = 0; ni < 4; ni++) {
            int r = bm + wm + mi * 16 + g;
            int c = bn + wn + ni * 8 + 2 * t;
            float b0 = bias[c], b1 = bias[c + 1];
            float o0 = acc[mi][ni][0] + b0, o1 = acc[mi][ni][1] + b1;
            float o2 = acc[mi][ni][2] + b0, o3 = acc[mi][ni][3] + b1;
            if (HOUT) {
                __half* C = (__half*)Cv;
                __half2 h0 = __floats2half2_rn(o0, o1);
                __half2 h1 = __floats2half2_rn(o2, o3);
                *(__half2*)(C + (size_t)r * ldc + c)       = h0;
                *(__half2*)(C + (size_t)(r + 8) * ldc + c) = h1;
            } else {
                float* C = (float*)Cv;
                *(float2*)(C + (size_t)r * ldc + c)       = make_float2(o0, o1);
                *(float2*)(C + (size_t)(r + 8) * ldc + c) = make_float2(o2, o3);
            }
        }
}

// ---------------- fused window attention: one block per (b,h) ---------------
// 512 threads, Q/K/V resident in smem, 4 chunks of 64 rows, exact softmax.
#define ATT_SMEM (256*40*2 + 256*40*2 + 32*264*2 + 64*260*4 + 4*64*36*4)

__global__ __launch_bounds__(512, 1) void attn_kernel(const float* __restrict__ mask) {
    extern __shared__ __align__(16) unsigned char smraw[];
    __half* Qh = (__half*)smraw;              // 256 x 40
    __half* Kh = Qh + 256 * 40;               // 256 x 40
    __half* VT = Kh + 256 * 40;               // 32 x 264   (V transposed [d][tok])
    float*  S  = (float*)(VT + 32 * 264);     // 64 x 260   (P halves reuse row fronts)
    float*  Rb = S + 64 * 260;                // 4 x 64 x 36 split-k partials

    const int h  = blockIdx.x;
    const int bw = blockIdx.y;
    const int w  = bw & 63;

    const int tid  = threadIdx.x;
    const int wid  = tid >> 5;
    const int lane = tid & 31;
    const int g    = lane >> 2;
    const int t    = lane & 3;

    const __half* base = g_qkv + (size_t)bw * 256 * 768 + h * 32;

    // ---- stage Q, K (cp.async, pure copies: scale folded into weights) ----
    uint32_t qb = (uint32_t)__cvta_generic_to_shared(Qh);
    uint32_t kb = (uint32_t)__cvta_generic_to_shared(Kh);
    #pragma unroll
    for (int j = 0; j < 2; j++) {
        int id  = tid + j * 512;
        int row = id >> 2, seg = id & 3;
        cp16(qb + row * 80 + seg * 16, base + (size_t)row * 768 + seg * 8);
        cp16(kb + row * 80 + seg * 16, base + (size_t)row * 768 + 256 + seg * 8);
    }
    cp_commit();

    // ---- stage V transposed ----
    #pragma unroll
    for (int it = 0; it < 8; it++) {
        int id  = tid + it * 512;
        int tok = id >> 4, dp = id & 15;
        __half2 v = *(const __half2*)(base + (size_t)tok * 768 + 512 + dp * 2);
        VT[(2 * dp) * 264 + tok]     = __low2half(v);
        VT[(2 * dp + 1) * 264 + tok] = __high2half(v);
    }
    cp_wait0();
    __syncthreads();

    const __half* Sh = (const __half*)S;

    #pragma unroll 1
    for (int ch = 0; ch < 4; ch++) {
        // ---- S = Q K^T (64 x 256): warps 2m x 8n, warp tile 32x32 ----
        {
            const int wm = (wid >> 3) * 32;
            const int wn = (wid & 7) * 32;
            float sacc[2][4][4];
            #pragma unroll
            for (int mi = 0; mi < 2; mi++)
                #pragma unroll
                for (int ni = 0; ni < 4; ni++)
                    #pragma unroll
                    for (int e = 0; e < 4; e++) sacc[mi][ni][e] = 0.f;

            #pragma unroll
            for (int kc = 0; kc < 2; kc++) {
                uint32_t af[2][4];
                #pragma unroll
                for (int mi = 0; mi < 2; mi++) {
                    const __half* p = Qh + (ch * 64 + wm + mi * 16 + g) * 40 + kc * 16 + 2 * t;
                    af[mi][0] = *(const uint32_t*)p;
                    af[mi][1] = *(const uint32_t*)(p + 8 * 40);
                    af[mi][2] = *(const uint32_t*)(p + 8);
                    af[mi][3] = *(const uint32_t*)(p + 8 * 40 + 8);
                }
                #pragma unroll
                for (int ni = 0; ni < 4; ni++) {
                    const __half* p = Kh + (wn + ni * 8 + g) * 40 + kc * 16 + 2 * t;
                    uint32_t bf[2];
                    bf[0] = *(const uint32_t*)p;
                    bf[1] = *(const uint32_t*)(p + 8);
                    mma16(sacc[0][ni], af[0], bf);
                    mma16(sacc[1][ni], af[1], bf);
                }
            }
            #pragma unroll
            for (int mi = 0; mi < 2; mi++)
                #pragma unroll
                for (int ni = 0; ni < 4; ni++) {
                    float* d = S + (wm + mi * 16 + g) * 260 + wn + ni * 8 + 2 * t;
                    *(float2*)d            = make_float2(sacc[mi][ni][0], sacc[mi][ni][1]);
                    *(float2*)(d + 8 * 260) = make_float2(sacc[mi][ni][2], sacc[mi][ni][3]);
                }
        }
        __syncthreads();

        // ---- exact softmax, +bias+mask; write P as half over row fronts ----
        #pragma unroll 1
        for (int rr = 0; rr < 4; rr++) {
            int r  = wid * 4 + rr;
            int ig = ch * 64 + r;
            const float* brow = g_bias + ((size_t)(h * 256 + ig)) * 256 + lane * 8;
            const float* mrow = mask + ((size_t)(w * 256 + ig)) * 256 + lane * 8;
            float* srow = S + r * 260 + lane * 8;
            float4 s0 = *(float4*)srow,          s1 = *(float4*)(srow + 4);
            float4 b0 = *(const float4*)brow,    b1 = *(const float4*)(brow + 4);
            float4 m0 = *(const float4*)mrow,    m1 = *(const float4*)(mrow + 4);
            float v[8];
            v[0] = s0.x + b0.x + m0.x; v[1] = s0.y + b0.y + m0.y;
            v[2] = s0.z + b0.z + m0.z; v[3] = s0.w + b0.w + m0.w;
            v[4] = s1.x + b1.x + m1.x; v[5] = s1.y + b1.y + m1.y;
            v[6] = s1.z + b1.z + m1.z; v[7] = s1.w + b1.w + m1.w;
            float mx = v[0];
            #pragma unroll
            for (int u = 1; u < 8; u++) mx = fmaxf(mx, v[u]);
            #pragma unroll
            for (int off = 16; off > 0; off >>= 1)
                mx = fmaxf(mx, __shfl_xor_sync(0xffffffffu, mx, off));
            float s = 0.f;
            #pragma unroll
            for (int u = 0; u < 8; u++) { v[u] = __expf(v[u] - mx); s += v[u]; }
            #pragma unroll
            for (int off = 16; off > 0; off >>= 1)
                s += __shfl_xor_sync(0xffffffffu, s, off);
            float inv = 1.f / s;
            __half2 p01 = __floats2half2_rn(v[0] * inv, v[1] * inv);
            __half2 p23 = __floats2half2_rn(v[2] * inv, v[3] * inv);
            __half2 p45 = __floats2half2_rn(v[4] * inv, v[5] * inv);
            __half2 p67 = __floats2half2_rn(v[6] * inv, v[7] * inv);
            uint4 u4;
            u4.x = *reinterpret_cast<uint32_t*>(&p01);
            u4.y = *reinterpret_cast<uint32_t*>(&p23);
            u4.z = *reinterpret_cast<uint32_t*>(&p45);
            u4.w = *reinterpret_cast<uint32_t*>(&p67);
            *(uint4*)((__half*)(S + r * 260) + lane * 8) = u4;
        }
        __syncthreads();

        // ---- O = P V (64 x 32), warps 2m x 2n x 4-way split-k ----
        {
            const int km = wid & 3;
            const int pn = (wid >> 2) & 1;
            const int pm = wid >> 3;
            float oacc[2][2][4];
            #pragma unroll
            for (int mi = 0; mi < 2; mi++)
                #pragma unroll
                for (int ni = 0; ni < 2; ni++)
                    #pragma unroll
                    for (int e = 0; e < 4; e++) oacc[mi][ni][e] = 0.f;

            #pragma unroll
            for (int kc = 0; kc < 4; kc++) {
                int k = km * 64 + kc * 16;
                uint32_t af[2][4];
                #pragma unroll
                for (int mi = 0; mi < 2; mi++) {
                    const __half* p = Sh + (size_t)(pm * 32 + mi * 16 + g) * 520 + k + 2 * t;
                    af[mi][0] = *(const uint32_t*)p;
                    af[mi][1] = *(const uint32_t*)(p + 8 * 520);
                    af[mi][2] = *(const uint32_t*)(p + 8);
                    af[mi][3] = *(const uint32_t*)(p + 8 * 520 + 8);
                }
                #pragma unroll
                for (int ni = 0; ni < 2; ni++) {
                    const __half* p = VT + (pn * 16 + ni * 8 + g) * 264 + k + 2 * t;
                    uint32_t bf[2];
                    bf[0] = *(const uint32_t*)p;
                    bf[1] = *(const uint32_t*)(p + 8);
                    mma16(oacc[0][ni], af[0], bf);
                    mma16(oacc[1][ni], af[1], bf);
                }
            }
            #pragma unroll
            for (int mi = 0; mi < 2; mi++)
                #pragma unroll
                for (int ni = 0; ni < 2; ni++) {
                    float* d = Rb + km * 2304 + (pm * 32 + mi * 16 + g) * 36 + pn * 16 + ni * 8 + 2 * t;
                    *(float2*)d           = make_float2(oacc[mi][ni][0], oacc[mi][ni][1]);
                    *(float2*)(d + 8 * 36) = make_float2(oacc[mi][ni][2], oacc[mi][ni][3]);
                }
        }
        __syncthreads();

        // ---- split-k reduce + half store ----
        {
            int row = tid >> 3;
            int dq  = tid & 7;
            float4 a0 = *(float4*)(Rb + 0 * 2304 + row * 36 + dq * 4);
            float4 a1 = *(float4*)(Rb + 1 * 2304 + row * 36 + dq * 4);
            float4 a2 = *(float4*)(Rb + 2 * 2304 + row * 36 + dq * 4);
            float4 a3 = *(float4*)(Rb + 3 * 2304 + row * 36 + dq * 4);
            float o0 = a0.x + a1.x + a2.x + a3.x;
            float o1 = a0.y + a1.y + a2.y + a3.y;
            float o2 = a0.z + a1.z + a2.z + a3.z;
            float o3 = a0.w + a1.w + a2.w + a3.w;
            __half2 h0 = __floats2half2_rn(o0, o1);
            __half2 h1 = __floats2half2_rn(o2, o3);
            uint2 u;
            u.x = *reinterpret_cast<uint32_t*>(&h0);
            u.y = *reinterpret_cast<uint32_t*>(&h1);
            __half* dst = g_attnout + ((size_t)(bw * 256 + ch * 64 + row)) * 256 + h * 32 + dq * 4;
            *(uint2*)dst = u;
        }
        __syncthreads();
    }
}

// ---------------- launch ----------------
extern "C" void kernel_launch(void* const* d_in, const int* in_sizes, int n_in,
                              void* d_out, int out_size)
{
    const float* x      = (const float*)d_in[0];
    const float* mask   = (const float*)d_in[1];
    const float* qkv_w  = (const float*)d_in[2];
    const float* qkv_b  = (const float*)d_in[3];
    const float* proj_w = (const float*)d_in[4];
    const float* proj_b = (const float*)d_in[5];
    const float* table  = (const float*)d_in[6];
    const int*   rpi    = (const int*)d_in[7];
    float* out = (float*)d_out;
    (void)in_sizes; (void)n_in; (void)out_size;

    __half *xh_p, *qkvwh_p, *projwh_p, *qkv_p, *ao_p;
    float *qkvb_p;
    cudaGetSymbolAddress((void**)&xh_p, g_xh);
    cudaGetSymbolAddress((void**)&qkvwh_p, g_qkvwh);
    cudaGetSymbolAddress((void**)&projwh_p, g_projwh);
    cudaGetSymbolAddress((void**)&qkv_p, g_qkv);
    cudaGetSymbolAddress((void**)&ao_p, g_attnout);
    cudaGetSymbolAddress((void**)&qkvb_p, g_qkvb);

    cudaFuncSetAttribute(attn_kernel, cudaFuncAttributeMaxDynamicSharedMemorySize, ATT_SMEM);

    // converts + bias gather
    cvt_x<<<12288, 256>>>((const float4*)x);
    cvt_qkvw<<<768, 256>>>(qkv_w, qkv_b);
    cvt_projw<<<256, 256>>>(proj_w);
    bias_kernel<<<2048, 256>>>(table, rpi);

    // QKV projection (half out), q pre-scaled
    gemm_h<true><<<dim3(384, 6), 256>>>(xh_p, qkvwh_p, qkvb_p, qkv_p, 768);

    // fused window attention (half out)
    attn_kernel<<<dim3(8, 192), 512, ATT_SMEM>>>(mask);

    // output projection (fp32 out)
    gemm_h<false><<<dim3(384, 2), 256>>>(ao_p, projwh_p, proj_b, out, 256);
}